// round 14
// baseline (speedup 1.0000x reference)
#include <cuda_runtime.h>
#include <cuda_fp16.h>
#include <math.h>
#include <stdint.h>

#define Bn 512
#define Tn 512
#define NBLK 128
#define NTHR 256

// ---- dynamic SMEM layout (bytes) ----
#define OFF_H(b)   ((b) * 16384)            // 4 h chunk bufs (fp16): 128 rows x 128B (SW128)
#define OFF_W      65536                    // W tile (fp16): 512 k-rows x 128B (SW128) = 64KB
#define OFF_WIH    131072                   // 64 floats
#define OFF_BIAS   131328                   // 64 floats
#define SMEM_BYTES 131584
// epilogue bounce regions (reuse buf0, free at that point)
#define BOUNCE_HH  0                        // 128x16 fp16 = 4KB
#define BOUNCE_HF  4096                     // 128x16 f32 = 8KB (final step only)

static __device__ __forceinline__ uint32_t sw128(uint32_t x) { return x ^ ((x >> 3) & 0x70); }

// ---- global scratch (no cudaMalloc allowed) ----
__device__ __half g_hh[2][Bn][512];          // h (fp16), ping-pong, [batch][hidden]
__device__ float g_seqT[Tn][Bn];
__device__ float g_hf[Bn][512];              // final fp32 h for MLP head
__device__ unsigned g_count = 0;
__device__ volatile unsigned g_gen = 0;

__device__ __forceinline__ uint32_t smem_u32(const void* p) {
    uint32_t a;
    asm("{ .reg .u64 t; cvta.to.shared.u64 t, %1; cvt.u32.u64 %0, t; }" : "=r"(a) : "l"(p));
    return a;
}
__device__ __forceinline__ void ldsm_x4(uint32_t* r, uint32_t addr) {
    asm volatile("ldmatrix.sync.aligned.m8n8.x4.shared.b16 {%0,%1,%2,%3}, [%4];"
                 : "=r"(r[0]), "=r"(r[1]), "=r"(r[2]), "=r"(r[3]) : "r"(addr));
}
__device__ __forceinline__ void ldsm_x4_t(uint32_t* r, uint32_t addr) {
    asm volatile("ldmatrix.sync.aligned.m8n8.x4.trans.shared.b16 {%0,%1,%2,%3}, [%4];"
                 : "=r"(r[0]), "=r"(r[1]), "=r"(r[2]), "=r"(r[3]) : "r"(addr));
}
__device__ __forceinline__ void mma_f16(float* d, const uint32_t* a, const uint32_t* b) {
    asm volatile(
        "mma.sync.aligned.m16n8k16.row.col.f32.f16.f16.f32 "
        "{%0,%1,%2,%3}, {%4,%5,%6,%7}, {%8,%9}, {%0,%1,%2,%3};"
        : "+f"(d[0]), "+f"(d[1]), "+f"(d[2]), "+f"(d[3])
        : "r"(a[0]), "r"(a[1]), "r"(a[2]), "r"(a[3]), "r"(b[0]), "r"(b[1]));
}
__device__ __forceinline__ void cp16(uint32_t dst, const void* src) {
    asm volatile("cp.async.cg.shared.global [%0], [%1], 16;"
                 :: "r"(dst), "l"(__cvta_generic_to_global(src)) : "memory");
}
__device__ __forceinline__ void cp_commit() {
    asm volatile("cp.async.commit_group;" ::: "memory");
}
template <int N>
__device__ __forceinline__ void cp_wait_group() {
    asm volatile("cp.async.wait_group %0;" :: "n"(N) : "memory");
}

// Flat grid barrier (measured cheaper than the R10 tree).
__device__ __forceinline__ void grid_sync(unsigned target) {
    __syncthreads();
    if (threadIdx.x == 0) {
        __threadfence();
        unsigned old = atomicAdd(&g_count, 1u);
        if (old == NBLK - 1) {
            g_count = 0;
            __threadfence();
            g_gen = target;
        } else {
            while (g_gen != target) { }
            __threadfence();
        }
    }
    __syncthreads();
}

// Exact sigmoid (EX2-based); tanh.approx only on the additive path (R10-validated).
__device__ __forceinline__ float sigf(float x)  { return __fdividef(1.0f, 1.0f + __expf(-x)); }
__device__ __forceinline__ float tanh_ap(float x) {
    float y;
    asm("tanh.approx.f32 %0, %1;" : "=f"(y) : "f"(x));
    return y;
}

__global__ __launch_bounds__(NTHR, 1)
void lstm_tc(const float* __restrict__ seq,
             const float* __restrict__ Wih,
             const float* __restrict__ Whh,
             const float* __restrict__ bih,
             const float* __restrict__ bhh)
{
    extern __shared__ char smem[];
    __shared__ unsigned s_base;
    const uint32_t sb = smem_u32(smem);
    const int tid  = threadIdx.x;
    const int w    = tid >> 5;
    const int lane = tid & 31;
    const int bi   = blockIdx.x >> 5;   // batch tile 0..3
    const int ji   = blockIdx.x & 31;   // hidden-slice tile 0..31 (16 units each)
    const int b0   = bi * 128;
    const int j0   = ji * 16;

    if (tid == 0) s_base = g_gen;

    // ---- W_hh tile -> SMEM, fp16, k-major [k][n], SW128 swizzle ----
    // local col n = jl*4+g  <->  global W row = g*512 + j0 + jl
    for (int idx = tid; idx < 64 * 512; idx += NTHR) {
        int n = idx >> 9, k = idx & 511;
        int row = (n & 3) * 512 + j0 + (n >> 2);
        float wv = Whh[(size_t)row * 512 + k];
        uint32_t so = sw128((uint32_t)k * 128 + n * 2);
        *(__half*)(smem + OFF_W + so) = __float2half_rn(wv);
    }
    if (tid < 64) {
        int jl = tid >> 2, g = tid & 3;
        int row = g * 512 + j0 + jl;
        ((float*)(smem + OFF_WIH))[tid]  = Wih[row];
        ((float*)(smem + OFF_BIAS))[tid] = bih[row] + bhh[row];
    }
    // zero h0 (buffer 0) and transpose sequence
    {
        int base = blockIdx.x * 2048;
        #pragma unroll
        for (int i = 0; i < 8; ++i) {
            int idx = base + i * NTHR + tid;
            ((__half*)g_hh)[idx] = __float2half_rn(0.0f);
            int b = idx >> 9, t = idx & 511;
            g_seqT[t][b] = seq[idx];
        }
    }
    grid_sync(s_base + 1);
    const unsigned base_gen = s_base;

    // ---- per-lane constants (8 warps: warp tile m32 x n32) ----
    const int wm = w & 3;                // batch quadrant (m32)
    const int wn = w >> 2;               // gate-col half (n32): 0 or 1
    const int l15 = lane & 15;
    const int lb  = lane >> 4;
    const uint32_t a_row  = (uint32_t)(wm * 32 + l15);
    const uint32_t a_xm   = a_row & 7;
    const uint32_t a_base = sb + a_row * 128;
    // B: two OFFSET-computed column bases (no address-level XOR — R11/R12 lesson).
    const uint32_t b_col16a = (uint32_t)(((wn * 4 + lb)     ^ (l15 & 7)));
    const uint32_t b_col16b = (uint32_t)(((wn * 4 + 2 + lb) ^ (l15 & 7)));
    const uint32_t b_base_a = sb + OFF_W + (uint32_t)l15 * 128 + b_col16a * 16;
    const uint32_t b_base_b = sb + OFF_W + (uint32_t)l15 * 128 + b_col16b * 16;

    // staging (cp.async dst): 256 threads, each copies 64B: row tid>>1, 64B half tid&1
    const int sm_r = tid >> 1, shf = tid & 1;
    const uint32_t sts_off = sw128((uint32_t)sm_r * 128 + shf * 64);
    // raw offset bits 4..5 are 0 -> sw128(x + {16,32,48}) == sw128(x) ^ {16,32,48} (offset-level)

    const float* wih_s  = (const float*)(smem + OFF_WIH);
    const float* bias_s = (const float*)(smem + OFF_BIAS);
    float bw_a[4], bw_b[4], wi_a[4], wi_b[4];
    #pragma unroll
    for (int nt = 0; nt < 4; ++nt) {
        int ca = wn * 32 + nt * 8 + (lane & 3) * 2;
        bw_a[nt] = bias_s[ca];     bw_b[nt] = bias_s[ca + 1];
        wi_a[nt] = wih_s[ca];      wi_b[nt] = wih_s[ca + 1];
    }
    const int q = lane & 1;
    const int rowm0 = wm * 32 + (lane >> 2);
    float cst[8];
    #pragma unroll
    for (int i = 0; i < 8; ++i) cst[i] = 0.f;

    for (int t = 0; t < Tn; ++t) {
        const int rb = t & 1, nb = rb ^ 1;

        // init accumulators with bias + x*W_ih (mma accumulates on top)
        float acc[2][4][4];
        #pragma unroll
        for (int mt = 0; mt < 2; ++mt) {
            float svA = g_seqT[t][b0 + rowm0 + mt * 16];
            float svB = g_seqT[t][b0 + rowm0 + mt * 16 + 8];
            #pragma unroll
            for (int nt = 0; nt < 4; ++nt) {
                acc[mt][nt][0] = fmaf(svA, wi_a[nt], bw_a[nt]);
                acc[mt][nt][1] = fmaf(svA, wi_b[nt], bw_b[nt]);
                acc[mt][nt][2] = fmaf(svB, wi_a[nt], bw_a[nt]);
                acc[mt][nt][3] = fmaf(svB, wi_b[nt], bw_b[nt]);
            }
        }

        // ---- 3-deep pipeline prologue: issue chunks 0,1,2 as separate groups ----
        #pragma unroll
        for (int p = 0; p < 3; ++p) {
            const __half* sh = &g_hh[rb][b0 + sm_r][p * 64 + shf * 32];
            const uint32_t d = sb + OFF_H(p);
            cp16(d + sts_off,        sh);
            cp16(d + (sts_off ^ 16), sh + 8);
            cp16(d + (sts_off ^ 32), sh + 16);
            cp16(d + (sts_off ^ 48), sh + 24);
            cp_commit();
        }

        #pragma unroll 1
        for (int kc = 0; kc < 8; ++kc) {
            // wait for chunk kc only (oldest outstanding group); exact at the tail:
            // outstanding at top = chunks kc..min(7,kc+2)
            if (kc <= 5)      cp_wait_group<2>();
            else if (kc == 6) cp_wait_group<1>();
            else              cp_wait_group<0>();
            __syncthreads();   // chunk kc visible to all; readers of buf (kc+3)&3 (chunk kc-1) done
            if (kc < 5) {
                const int nbuf = (kc + 3) & 3;
                const __half* sh = &g_hh[rb][b0 + sm_r][(kc + 3) * 64 + shf * 32];
                const uint32_t d = sb + OFF_H(nbuf);
                cp16(d + sts_off,        sh);
                cp16(d + (sts_off ^ 16), sh + 8);
                cp16(d + (sts_off ^ 32), sh + 16);
                cp16(d + (sts_off ^ 48), sh + 24);
                cp_commit();
            }

            const uint32_t abuf = a_base + OFF_H(kc & 3);
            const uint32_t bka  = b_base_a + (uint32_t)kc * 8192;
            const uint32_t bkb  = b_base_b + (uint32_t)kc * 8192;
            #pragma unroll
            for (int kq = 0; kq < 4; ++kq) {
                const uint32_t acol = (uint32_t)(((kq * 2 + lb) ^ a_xm)) << 4;
                uint32_t ah0[4], ah1[4], b0r[4], b1r[4];
                ldsm_x4(ah0, abuf + acol);                        // A m16 #0, k16
                ldsm_x4(ah1, abuf + 2048 + acol);                 // A m16 #1
                ldsm_x4_t(b0r, bka + (uint32_t)kq * 2048);        // W k16 x n16 (cols 0..15)
                ldsm_x4_t(b1r, bkb + (uint32_t)kq * 2048);        // W k16 x n16 (cols 16..31)
                // 8 HMMA per kq
                mma_f16(acc[0][0], ah0, b0r);  mma_f16(acc[0][1], ah0, b0r + 2);
                mma_f16(acc[0][2], ah0, b1r);  mma_f16(acc[0][3], ah0, b1r + 2);
                mma_f16(acc[1][0], ah1, b0r);  mma_f16(acc[1][1], ah1, b0r + 2);
                mma_f16(acc[1][2], ah1, b1r);  mma_f16(acc[1][3], ah1, b1r + 2);
            }
        }

        __syncthreads();   // all chunk reads done; pipeline drained -> buf0 reusable as bounce

        // ---- LSTM cell epilogue: lane pairs exchange (i,f)<->(g,o) ----
        #pragma unroll
        for (int mt = 0; mt < 2; ++mt) {
            #pragma unroll
            for (int nt = 0; nt < 4; ++nt) {
                float x0 = __shfl_xor_sync(0xffffffffu, acc[mt][nt][0], 1);
                float x1 = __shfl_xor_sync(0xffffffffu, acc[mt][nt][1], 1);
                float x2 = __shfl_xor_sync(0xffffffffu, acc[mt][nt][2], 1);
                float x3 = __shfl_xor_sync(0xffffffffu, acc[mt][nt][3], 1);
                float gi, gf, gg, go;
                int rowl;
                if (q == 0) { gi = acc[mt][nt][0]; gf = acc[mt][nt][1]; gg = x0; go = x1;
                              rowl = rowm0 + mt * 16; }
                else        { gi = x2; gf = x3; gg = acc[mt][nt][2]; go = acc[mt][nt][3];
                              rowl = rowm0 + mt * 16 + 8; }
                const int ci = mt * 4 + nt;
                cst[ci] = sigf(gf) * cst[ci] + sigf(gi) * tanh_ap(gg);
                float h = sigf(go) * tanh_ap(cst[ci]);
                int ul = wn * 8 + nt * 2 + ((lane & 3) >> 1);   // local unit 0..15
                *(__half*)(smem + BOUNCE_HH + rowl * 32 + ul * 2) = __float2half_rn(h);
                if (t == Tn - 1)
                    *(float*)(smem + BOUNCE_HF + rowl * 64 + ul * 4) = h;
            }
        }
        __syncthreads();
        // coalesced write-out of this CTA's 128x16 h slice (256 thr: 16B each)
        if (t < Tn - 1) {
            uint4 hv = *(uint4*)(smem + BOUNCE_HH + sm_r * 32 + shf * 16);
            *(uint4*)&g_hh[nb][b0 + sm_r][j0 + shf * 8] = hv;
        } else {
            float4 f0 = *(float4*)(smem + BOUNCE_HF + sm_r * 64 + shf * 32);
            float4 f1 = *(float4*)(smem + BOUNCE_HF + sm_r * 64 + shf * 32 + 16);
            *(float4*)&g_hf[b0 + sm_r][j0 + shf * 8]     = f0;
            *(float4*)&g_hf[b0 + sm_r][j0 + shf * 8 + 4] = f1;
        }
        grid_sync(base_gen + 2 + t);
    }
}

__global__ __launch_bounds__(256)
void mlp_head(const float* __restrict__ fc1w, const float* __restrict__ fc1b,
              const float* __restrict__ fc2w, const float* __restrict__ fc2b,
              float* __restrict__ out)
{
    __shared__ float hcol[512];
    __shared__ float z[256];
    const int b = blockIdx.x;
    const int tid = threadIdx.x;

    hcol[tid]       = g_hf[b][tid];
    hcol[tid + 256] = g_hf[b][tid + 256];
    __syncthreads();

    float acc = fc1b[tid];
    const float4* w4 = (const float4*)(fc1w + (size_t)tid * 512);
    const float4* h4 = (const float4*)hcol;
    #pragma unroll 4
    for (int k = 0; k < 128; ++k) {
        float4 wv = w4[k], hv = h4[k];
        acc = fmaf(wv.x, hv.x, acc); acc = fmaf(wv.y, hv.y, acc);
        acc = fmaf(wv.z, hv.z, acc); acc = fmaf(wv.w, hv.w, acc);
    }
    z[tid] = fmaxf(acc, 0.0f);
    __syncthreads();

    if (tid < 28) {
        float o = fc2b[tid];
        const float4* w4b = (const float4*)(fc2w + (size_t)tid * 256);
        const float4* z4  = (const float4*)z;
        #pragma unroll 4
        for (int k = 0; k < 64; ++k) {
            float4 wv = w4b[k], zz = z4[k];
            o = fmaf(wv.x, zz.x, o); o = fmaf(wv.y, zz.y, o);
            o = fmaf(wv.z, zz.z, o); o = fmaf(wv.w, zz.w, o);
        }
        out[b * 28 + tid] = o;
    }
}

extern "C" void kernel_launch(void* const* d_in, const int* in_sizes, int n_in,
                              void* d_out, int out_size) {
    const float* seq  = (const float*)d_in[0];
    const float* Wih  = (const float*)d_in[1];
    const float* Whh  = (const float*)d_in[2];
    const float* bih  = (const float*)d_in[3];
    const float* bhh  = (const float*)d_in[4];
    const float* fc1w = (const float*)d_in[5];
    const float* fc1b = (const float*)d_in[6];
    const float* fc2w = (const float*)d_in[7];
    const float* fc2b = (const float*)d_in[8];
    float* out = (float*)d_out;

    cudaFuncSetAttribute(lstm_tc, cudaFuncAttributeMaxDynamicSharedMemorySize, SMEM_BYTES);
    lstm_tc<<<NBLK, NTHR, SMEM_BYTES>>>(seq, Wih, Whh, bih, bhh);
    mlp_head<<<Bn, 256>>>(fc1w, fc1b, fc2w, fc2b, out);
}

// round 15
// speedup vs baseline: 1.2054x; 1.2054x over previous
#include <cuda_runtime.h>
#include <cuda_fp16.h>
#include <math.h>
#include <stdint.h>

#define Bn 512
#define Tn 512
#define NBLK 256          // 8 batch groups x 32 gate slices
#define NTHR 128
#define GRP 32            // CTAs per barrier group

// ---- dynamic SMEM layout (bytes) ----
#define OFF_H(b)   ((b) * 8192)             // 2 h chunk bufs (fp16): 64 rows x 128B (SW128)
#define OFF_W      16384                    // W tile (fp16): 512 k-rows x 128B (SW128) = 64KB
#define OFF_WIH    81920                    // 64 floats
#define OFF_BIAS   82176                    // 64 floats
#define SMEM_BYTES 82432                    // x2 CTAs = 161KB/SM < 228KB
// epilogue bounce regions (reuse buf0, free at that point)
#define BOUNCE_HH  0                        // 64x16 fp16 = 2KB
#define BOUNCE_HF  4096                     // 64x16 f32 = 4KB (final step only)

static __device__ __forceinline__ uint32_t sw128(uint32_t x) { return x ^ ((x >> 3) & 0x70); }

// ---- global scratch (no cudaMalloc allowed) ----
__device__ __half g_hh[2][Bn][512];          // h (fp16), ping-pong, [batch][hidden]
__device__ float g_seqT[Tn][Bn];
__device__ float g_hf[Bn][512];              // final fp32 h for MLP head
__device__ unsigned g_icount = 0;            // one-time global init barrier
__device__ volatile unsigned g_igen = 0;
__device__ unsigned g_gcount[8][32];         // per-group counters (128B apart)
__device__ volatile unsigned g_ggen[8][32];  // per-group release gens

__device__ __forceinline__ uint32_t smem_u32(const void* p) {
    uint32_t a;
    asm("{ .reg .u64 t; cvta.to.shared.u64 t, %1; cvt.u32.u64 %0, t; }" : "=r"(a) : "l"(p));
    return a;
}
__device__ __forceinline__ void ldsm_x4(uint32_t* r, uint32_t addr) {
    asm volatile("ldmatrix.sync.aligned.m8n8.x4.shared.b16 {%0,%1,%2,%3}, [%4];"
                 : "=r"(r[0]), "=r"(r[1]), "=r"(r[2]), "=r"(r[3]) : "r"(addr));
}
__device__ __forceinline__ void ldsm_x4_t(uint32_t* r, uint32_t addr) {
    asm volatile("ldmatrix.sync.aligned.m8n8.x4.trans.shared.b16 {%0,%1,%2,%3}, [%4];"
                 : "=r"(r[0]), "=r"(r[1]), "=r"(r[2]), "=r"(r[3]) : "r"(addr));
}
__device__ __forceinline__ void mma_f16(float* d, const uint32_t* a, const uint32_t* b) {
    asm volatile(
        "mma.sync.aligned.m16n8k16.row.col.f32.f16.f16.f32 "
        "{%0,%1,%2,%3}, {%4,%5,%6,%7}, {%8,%9}, {%0,%1,%2,%3};"
        : "+f"(d[0]), "+f"(d[1]), "+f"(d[2]), "+f"(d[3])
        : "r"(a[0]), "r"(a[1]), "r"(a[2]), "r"(a[3]), "r"(b[0]), "r"(b[1]));
}
__device__ __forceinline__ void cp16(uint32_t dst, const void* src) {
    asm volatile("cp.async.cg.shared.global [%0], [%1], 16;"
                 :: "r"(dst), "l"(__cvta_generic_to_global(src)) : "memory");
}
__device__ __forceinline__ void cp_commit() {
    asm volatile("cp.async.commit_group;" ::: "memory");
}
__device__ __forceinline__ void cp_wait0() {
    asm volatile("cp.async.wait_group 0;" ::: "memory");
}

// One-time global barrier across all 256 CTAs (init data visibility).
__device__ __forceinline__ void init_sync(unsigned target) {
    __syncthreads();
    if (threadIdx.x == 0) {
        __threadfence();
        unsigned old = atomicAdd(&g_icount, 1u);
        if (old == NBLK - 1) {
            g_icount = 0;
            __threadfence();
            g_igen = target;
        } else {
            while (g_igen != target) { }
            __threadfence();
        }
    }
    __syncthreads();
}

// Per-batch-group barrier (32 CTAs) — groups are independent between steps.
__device__ __forceinline__ void group_sync(unsigned target, int grp) {
    __syncthreads();
    if (threadIdx.x == 0) {
        __threadfence();
        unsigned old = atomicAdd(&g_gcount[grp][0], 1u);
        if (old == GRP - 1) {
            g_gcount[grp][0] = 0;
            __threadfence();
            g_ggen[grp][0] = target;
        } else {
            while (g_ggen[grp][0] != target) { }
            __threadfence();
        }
    }
    __syncthreads();
}

// Exact sigmoid (EX2-based); tanh.approx only on the additive path (R10-validated).
__device__ __forceinline__ float sigf(float x)  { return __fdividef(1.0f, 1.0f + __expf(-x)); }
__device__ __forceinline__ float tanh_ap(float x) {
    float y;
    asm("tanh.approx.f32 %0, %1;" : "=f"(y) : "f"(x));
    return y;
}

__global__ __launch_bounds__(NTHR, 2)
void lstm_tc(const float* __restrict__ seq,
             const float* __restrict__ Wih,
             const float* __restrict__ Whh,
             const float* __restrict__ bih,
             const float* __restrict__ bhh)
{
    extern __shared__ char smem[];
    __shared__ unsigned s_ibase, s_gbase;
    const uint32_t sb = smem_u32(smem);
    const int tid  = threadIdx.x;
    const int w    = tid >> 5;
    const int lane = tid & 31;
    const int bi   = blockIdx.x >> 5;   // batch group 0..7 (64 rows each)
    const int ji   = blockIdx.x & 31;   // hidden-slice tile 0..31 (16 units each)
    const int b0   = bi * 64;
    const int j0   = ji * 16;

    if (tid == 0) { s_ibase = g_igen; s_gbase = g_ggen[bi][0]; }

    // ---- W_hh tile -> SMEM, fp16, k-major [k][n], SW128 swizzle ----
    // local col n = jl*4+g  <->  global W row = g*512 + j0 + jl
    for (int idx = tid; idx < 64 * 512; idx += NTHR) {
        int n = idx >> 9, k = idx & 511;
        int row = (n & 3) * 512 + j0 + (n >> 2);
        float wv = Whh[(size_t)row * 512 + k];
        uint32_t so = sw128((uint32_t)k * 128 + n * 2);
        *(__half*)(smem + OFF_W + so) = __float2half_rn(wv);
    }
    if (tid < 64) {
        int jl = tid >> 2, g = tid & 3;
        int row = g * 512 + j0 + jl;
        ((float*)(smem + OFF_WIH))[tid]  = Wih[row];
        ((float*)(smem + OFF_BIAS))[tid] = bih[row] + bhh[row];
    }
    // zero h0 (buffer 0) and transpose sequence (global coverage -> global init barrier)
    {
        int base = blockIdx.x * 1024;
        #pragma unroll
        for (int i = 0; i < 8; ++i) {
            int idx = base + i * NTHR + tid;
            ((__half*)g_hh)[idx] = __float2half_rn(0.0f);
            int b = idx >> 9, t = idx & 511;
            g_seqT[t][b] = seq[idx];
        }
    }
    init_sync(s_ibase + 1);
    const unsigned gbase = s_gbase;

    // ---- per-lane constants (4 warps: warp tile m32 x n32 over 64x64 D tile) ----
    const int wm = w & 1;                // batch half (m32)
    const int wn = w >> 1;               // gate-col half (n32): 0 or 1
    const int l15 = lane & 15;
    const int lb  = lane >> 4;
    const uint32_t a_row  = (uint32_t)(wm * 32 + l15);
    const uint32_t a_xm   = a_row & 7;
    const uint32_t a_base = sb + a_row * 128;
    // B: two OFFSET-computed column bases (no address-level XOR — R11/R12 lesson).
    const uint32_t b_col16a = (uint32_t)(((wn * 4 + lb)     ^ (l15 & 7)));
    const uint32_t b_col16b = (uint32_t)(((wn * 4 + 2 + lb) ^ (l15 & 7)));
    const uint32_t b_base_a = sb + OFF_W + (uint32_t)l15 * 128 + b_col16a * 16;
    const uint32_t b_base_b = sb + OFF_W + (uint32_t)l15 * 128 + b_col16b * 16;

    // staging (cp.async dst): 128 threads, each copies 64B: row tid>>1 (0..63), half tid&1
    const int sm_r = tid >> 1, shf = tid & 1;
    const uint32_t sts_off = sw128((uint32_t)sm_r * 128 + shf * 64);
    // raw offset bits 4..5 are 0 -> sw128(x + {16,32,48}) == sw128(x) ^ {16,32,48} (offset-level)

    const float* wih_s  = (const float*)(smem + OFF_WIH);
    const float* bias_s = (const float*)(smem + OFF_BIAS);
    float bw_a[4], bw_b[4], wi_a[4], wi_b[4];
    #pragma unroll
    for (int nt = 0; nt < 4; ++nt) {
        int ca = wn * 32 + nt * 8 + (lane & 3) * 2;
        bw_a[nt] = bias_s[ca];     bw_b[nt] = bias_s[ca + 1];
        wi_a[nt] = wih_s[ca];      wi_b[nt] = wih_s[ca + 1];
    }
    const int q = lane & 1;
    const int rowm0 = wm * 32 + (lane >> 2);
    float cst[8];
    #pragma unroll
    for (int i = 0; i < 8; ++i) cst[i] = 0.f;

    for (int t = 0; t < Tn; ++t) {
        const int rb = t & 1, nb = rb ^ 1;

        // init accumulators with bias + x*W_ih (mma accumulates on top)
        float acc[2][4][4];
        #pragma unroll
        for (int mt = 0; mt < 2; ++mt) {
            float svA = g_seqT[t][b0 + rowm0 + mt * 16];
            float svB = g_seqT[t][b0 + rowm0 + mt * 16 + 8];
            #pragma unroll
            for (int nt = 0; nt < 4; ++nt) {
                acc[mt][nt][0] = fmaf(svA, wi_a[nt], bw_a[nt]);
                acc[mt][nt][1] = fmaf(svA, wi_b[nt], bw_b[nt]);
                acc[mt][nt][2] = fmaf(svB, wi_a[nt], bw_a[nt]);
                acc[mt][nt][3] = fmaf(svB, wi_b[nt], bw_b[nt]);
            }
        }

        // stage chunk 0 into buf 0 (h visible after group barrier)
        {
            const __half* sh = &g_hh[rb][b0 + sm_r][shf * 32];
            cp16(sb + OFF_H(0) + sts_off,        sh);
            cp16(sb + OFF_H(0) + (sts_off ^ 16), sh + 8);
            cp16(sb + OFF_H(0) + (sts_off ^ 32), sh + 16);
            cp16(sb + OFF_H(0) + (sts_off ^ 48), sh + 24);
            cp_commit();
        }

        #pragma unroll 1
        for (int kc = 0; kc < 8; ++kc) {
            cp_wait0();
            __syncthreads();      // chunk kc visible; prior reads of other buf done
            if (kc < 7) {
                const int nbuf = (kc + 1) & 1;
                const __half* sh = &g_hh[rb][b0 + sm_r][(kc + 1) * 64 + shf * 32];
                cp16(sb + OFF_H(nbuf) + sts_off,        sh);
                cp16(sb + OFF_H(nbuf) + (sts_off ^ 16), sh + 8);
                cp16(sb + OFF_H(nbuf) + (sts_off ^ 32), sh + 16);
                cp16(sb + OFF_H(nbuf) + (sts_off ^ 48), sh + 24);
                cp_commit();
            }

            const uint32_t abuf = a_base + OFF_H(kc & 1);
            const uint32_t bka  = b_base_a + (uint32_t)kc * 8192;
            const uint32_t bkb  = b_base_b + (uint32_t)kc * 8192;
            #pragma unroll
            for (int kq = 0; kq < 4; ++kq) {
                const uint32_t acol = (uint32_t)(((kq * 2 + lb) ^ a_xm)) << 4;
                uint32_t ah0[4], ah1[4], b0r[4], b1r[4];
                ldsm_x4(ah0, abuf + acol);                        // A m16 #0, k16
                ldsm_x4(ah1, abuf + 2048 + acol);                 // A m16 #1
                ldsm_x4_t(b0r, bka + (uint32_t)kq * 2048);        // W k16 x n16 (cols 0..15)
                ldsm_x4_t(b1r, bkb + (uint32_t)kq * 2048);        // W k16 x n16 (cols 16..31)
                // 8 HMMA per kq
                mma_f16(acc[0][0], ah0, b0r);  mma_f16(acc[0][1], ah0, b0r + 2);
                mma_f16(acc[0][2], ah0, b1r);  mma_f16(acc[0][3], ah0, b1r + 2);
                mma_f16(acc[1][0], ah1, b0r);  mma_f16(acc[1][1], ah1, b0r + 2);
                mma_f16(acc[1][2], ah1, b1r);  mma_f16(acc[1][3], ah1, b1r + 2);
            }
        }

        __syncthreads();   // all chunk reads done -> buf0 reusable as bounce

        // ---- LSTM cell epilogue: lane pairs exchange (i,f)<->(g,o) ----
        #pragma unroll
        for (int mt = 0; mt < 2; ++mt) {
            #pragma unroll
            for (int nt = 0; nt < 4; ++nt) {
                float x0 = __shfl_xor_sync(0xffffffffu, acc[mt][nt][0], 1);
                float x1 = __shfl_xor_sync(0xffffffffu, acc[mt][nt][1], 1);
                float x2 = __shfl_xor_sync(0xffffffffu, acc[mt][nt][2], 1);
                float x3 = __shfl_xor_sync(0xffffffffu, acc[mt][nt][3], 1);
                float gi, gf, gg, go;
                int rowl;
                if (q == 0) { gi = acc[mt][nt][0]; gf = acc[mt][nt][1]; gg = x0; go = x1;
                              rowl = rowm0 + mt * 16; }
                else        { gi = x2; gf = x3; gg = acc[mt][nt][2]; go = acc[mt][nt][3];
                              rowl = rowm0 + mt * 16 + 8; }
                const int ci = mt * 4 + nt;
                cst[ci] = sigf(gf) * cst[ci] + sigf(gi) * tanh_ap(gg);
                float h = sigf(go) * tanh_ap(cst[ci]);
                int ul = wn * 8 + nt * 2 + ((lane & 3) >> 1);   // local unit 0..15
                *(__half*)(smem + BOUNCE_HH + rowl * 32 + ul * 2) = __float2half_rn(h);
                if (t == Tn - 1)
                    *(float*)(smem + BOUNCE_HF + rowl * 64 + ul * 4) = h;
            }
        }
        __syncthreads();
        // coalesced write-out of this CTA's 64x16 h slice (128 thr: 16B each)
        if (t < Tn - 1) {
            uint4 hv = *(uint4*)(smem + BOUNCE_HH + sm_r * 32 + shf * 16);
            *(uint4*)&g_hh[nb][b0 + sm_r][j0 + shf * 8] = hv;
        } else {
            float4 f0 = *(float4*)(smem + BOUNCE_HF + sm_r * 64 + shf * 32);
            float4 f1 = *(float4*)(smem + BOUNCE_HF + sm_r * 64 + shf * 32 + 16);
            *(float4*)&g_hf[b0 + sm_r][j0 + shf * 8]     = f0;
            *(float4*)&g_hf[b0 + sm_r][j0 + shf * 8 + 4] = f1;
        }
        group_sync(gbase + 1 + t, bi);
    }
}

__global__ __launch_bounds__(256)
void mlp_head(const float* __restrict__ fc1w, const float* __restrict__ fc1b,
              const float* __restrict__ fc2w, const float* __restrict__ fc2b,
              float* __restrict__ out)
{
    __shared__ float hcol[512];
    __shared__ float z[256];
    const int b = blockIdx.x;
    const int tid = threadIdx.x;

    hcol[tid]       = g_hf[b][tid];
    hcol[tid + 256] = g_hf[b][tid + 256];
    __syncthreads();

    float acc = fc1b[tid];
    const float4* w4 = (const float4*)(fc1w + (size_t)tid * 512);
    const float4* h4 = (const float4*)hcol;
    #pragma unroll 4
    for (int k = 0; k < 128; ++k) {
        float4 wv = w4[k], hv = h4[k];
        acc = fmaf(wv.x, hv.x, acc); acc = fmaf(wv.y, hv.y, acc);
        acc = fmaf(wv.z, hv.z, acc); acc = fmaf(wv.w, hv.w, acc);
    }
    z[tid] = fmaxf(acc, 0.0f);
    __syncthreads();

    if (tid < 28) {
        float o = fc2b[tid];
        const float4* w4b = (const float4*)(fc2w + (size_t)tid * 256);
        const float4* z4  = (const float4*)z;
        #pragma unroll 4
        for (int k = 0; k < 64; ++k) {
            float4 wv = w4b[k], zz = z4[k];
            o = fmaf(wv.x, zz.x, o); o = fmaf(wv.y, zz.y, o);
            o = fmaf(wv.z, zz.z, o); o = fmaf(wv.w, zz.w, o);
        }
        out[b * 28 + tid] = o;
    }
}

extern "C" void kernel_launch(void* const* d_in, const int* in_sizes, int n_in,
                              void* d_out, int out_size) {
    const float* seq  = (const float*)d_in[0];
    const float* Wih  = (const float*)d_in[1];
    const float* Whh  = (const float*)d_in[2];
    const float* bih  = (const float*)d_in[3];
    const float* bhh  = (const float*)d_in[4];
    const float* fc1w = (const float*)d_in[5];
    const float* fc1b = (const float*)d_in[6];
    const float* fc2w = (const float*)d_in[7];
    const float* fc2b = (const float*)d_in[8];
    float* out = (float*)d_out;

    cudaFuncSetAttribute(lstm_tc, cudaFuncAttributeMaxDynamicSharedMemorySize, SMEM_BYTES);
    lstm_tc<<<NBLK, NTHR, SMEM_BYTES>>>(seq, Wih, Whh, bih, bhh);
    mlp_head<<<Bn, 256>>>(fc1w, fc1b, fc2w, fc2b, out);
}